// round 6
// baseline (speedup 1.0000x reference)
#include <cuda_runtime.h>

// KLLoss: mean over rows of -sum_y t[r,y] * log_softmax(p[r])[y]
// N = 4194304 rows, C = 10, fp32. 335.5MB read -> ~42us DRAM floor.
//
// R6 (= R5 resubmit after infra failure): persistent looped warps +
// double-buffered prefetch. 4096 warps x 16 tiles (tile = 160 float4 =
// 64 rows, consecutive per warp). Prefetch of tile i+1 issues before the
// shuffle-gather of tile i -> loads always in flight; one block-reduce /
// atomic per block instead of per tile.
//
// Row math (per tile, as R4): chunk q: q%5 in {0,1}->rowA, 2->split, {3,4}->rowB
//   rowA = lo(q)+lo(q+1)+lo(q+2) at owner m==0; rowB = hi(q)+lo(q+1)+lo(q+2)
//   at owner m==2. Lanes 30/31 wrap into slot j+1 (guard j<4 exact).

#define C 10
#define THREADS 128
#define WARPS_PER_BLOCK 4
#define GRID 1024
#define TILES_PER_WARP 16
#define F4_PER_TILE 160                        // 64 rows

__device__ float        g_partials[GRID];
__device__ unsigned int g_count = 0;           // atomicInc wraps -> graph-replay safe

__device__ __forceinline__ void load_tile(const float4* __restrict__ pred4,
                                          const float4* __restrict__ tgt4,
                                          int base, int lane,
                                          float4 P[5], float4 T[5])
{
    #pragma unroll
    for (int j = 0; j < 5; j++) {
        P[j] = __ldcs(pred4 + base + 32 * j + lane);
        T[j] = __ldcs(tgt4  + base + 32 * j + lane);
    }
}

__device__ __forceinline__ void process_tile(const float4 P[5], const float4 T[5],
                                             int lane, int idx1, int idx2,
                                             float& acc, float& dp)
{
    const unsigned FULL = 0xFFFFFFFFu;
    float lo_e[5], hi_e[5], lo_t[5], hi_t[5];
    #pragma unroll
    for (int j = 0; j < 5; j++) {
        float4 p = P[j], t = T[j];
        float e0 = __expf(p.x), e1 = __expf(p.y);
        float e2 = __expf(p.z), e3 = __expf(p.w);
        dp = fmaf(t.x, p.x, fmaf(t.y, p.y, fmaf(t.z, p.z, fmaf(t.w, p.w, dp))));

        int m = (2 * j + lane) % 5;            // q%5, q = 32j + lane
        bool split = (m == 2);
        float e23 = e2 + e3, t23 = t.z + t.w;
        lo_e[j] = e0 + e1 + (split ? 0.0f : e23);
        hi_e[j] = split ? e23 : 0.0f;
        lo_t[j] = t.x + t.y + (split ? 0.0f : t23);
        hi_t[j] = split ? t23 : 0.0f;
    }
    #pragma unroll
    for (int j = 0; j < 5; j++) {
        float a1e = __shfl_sync(FULL, lo_e[j], idx1);
        float a2e = __shfl_sync(FULL, lo_e[j], idx2);
        float a1t = __shfl_sync(FULL, lo_t[j], idx1);
        float a2t = __shfl_sync(FULL, lo_t[j], idx2);
        float b1e = 0.0f, b2e = 0.0f, b1t = 0.0f, b2t = 0.0f;
        if (j < 4) {                           // slot-wrap, never needed at j==4
            b1e = __shfl_sync(FULL, lo_e[j + 1], idx1);
            b2e = __shfl_sync(FULL, lo_e[j + 1], idx2);
            b1t = __shfl_sync(FULL, lo_t[j + 1], idx1);
            b2t = __shfl_sync(FULL, lo_t[j + 1], idx2);
        }
        float n1e = (lane < 31) ? a1e : b1e;
        float n2e = (lane < 30) ? a2e : b2e;
        float n1t = (lane < 31) ? a1t : b1t;
        float n2t = (lane < 30) ? a2t : b2t;

        int m = (2 * j + lane) % 5;
        if (m == 0)
            acc += __logf(lo_e[j] + n1e + n2e) * (lo_t[j] + n1t + n2t);
        if (m == 2)
            acc += __logf(hi_e[j] + n1e + n2e) * (hi_t[j] + n1t + n2t);
    }
}

__global__ __launch_bounds__(THREADS) void kl_loss_kernel(
    const float4* __restrict__ pred4,
    const float4* __restrict__ tgt4,
    float* __restrict__ out,
    float inv_n)
{
    __shared__ float ws[WARPS_PER_BLOCK];
    __shared__ bool  s_last;

    const int tid  = threadIdx.x;
    const int lane = tid & 31;
    const int wid  = tid >> 5;
    const unsigned FULL = 0xFFFFFFFFu;
    const int idx1 = (lane + 1) & 31;
    const int idx2 = (lane + 2) & 31;

    const int w     = blockIdx.x * WARPS_PER_BLOCK + wid;    // 0..4095
    const int base0 = w * (TILES_PER_WARP * F4_PER_TILE);    // 2560 f4 per warp

    float acc = 0.0f, dp = 0.0f;
    float4 Pa[5], Ta[5], Pb[5], Tb[5];

    // Pipeline: A holds tile 2k, B holds tile 2k+1. Prefetch before gather.
    load_tile(pred4, tgt4, base0, lane, Pa, Ta);
    #pragma unroll 1
    for (int k = 0; k < TILES_PER_WARP / 2; k++) {
        int b1 = base0 + (2 * k + 1) * F4_PER_TILE;
        load_tile(pred4, tgt4, b1, lane, Pb, Tb);            // prefetch 2k+1
        process_tile(Pa, Ta, lane, idx1, idx2, acc, dp);     // consume 2k
        if (k < TILES_PER_WARP / 2 - 1) {
            int b2 = base0 + (2 * k + 2) * F4_PER_TILE;
            load_tile(pred4, tgt4, b2, lane, Pa, Ta);        // prefetch 2k+2
        }
        process_tile(Pb, Tb, lane, idx1, idx2, acc, dp);     // consume 2k+1
    }
    acc -= dp;

    // ---- Block reduce (once per block) ----
    #pragma unroll
    for (int off = 16; off > 0; off >>= 1)
        acc += __shfl_xor_sync(FULL, acc, off);
    if (lane == 0) ws[wid] = acc;
    __syncthreads();

    if (tid == 0) {
        float bsum = ws[0] + ws[1] + ws[2] + ws[3];
        g_partials[blockIdx.x] = bsum;
        __threadfence();
        unsigned old = atomicInc(&g_count, GRID - 1);        // self-resets
        s_last = (old == GRID - 1);
    }
    __syncthreads();

    // ---- Last block: final reduction ----
    if (s_last) {
        float v = 0.0f;
        #pragma unroll
        for (int i = 0; i < GRID / THREADS; i++)
            v += __ldcg(&g_partials[tid + i * THREADS]);
        #pragma unroll
        for (int off = 16; off > 0; off >>= 1)
            v += __shfl_xor_sync(FULL, v, off);
        if (lane == 0) ws[wid] = v;
        __syncthreads();
        if (tid < 32) {
            float x = (tid < WARPS_PER_BLOCK) ? ws[tid] : 0.0f;
            #pragma unroll
            for (int off = 2; off > 0; off >>= 1)
                x += __shfl_xor_sync(FULL, x, off);
            if (tid == 0) out[0] = x * inv_n;
        }
    }
}

extern "C" void kernel_launch(void* const* d_in, const int* in_sizes, int n_in,
                              void* d_out, int out_size) {
    const float4* pred = (const float4*)d_in[0];
    const float4* tgt  = (const float4*)d_in[1];
    float* out = (float*)d_out;

    int n_rows  = in_sizes[0] / C;            // 4,194,304
    float inv_n = 1.0f / (float)n_rows;
    // 4096 warps x 16 tiles x 160 f4 = 10,485,760 = exact coverage
    kl_loss_kernel<<<GRID, THREADS>>>(pred, tgt, out, inv_n);
}